// round 8
// baseline (speedup 1.0000x reference)
#include <cuda_runtime.h>
#include <math.h>

#define BB 4
#define TT 4096
#define DM 1024
#define HD 128
#define TK 1024          // pooled keys per batch (T/STRIDE)
#define NEGF (-1e30f)

// ------------------- scratch (static device globals; no allocs) -------------------
__device__ float g_Q [BB * TT * HD];   // RoPE'd, pre-scaled Q:  8 MB
__device__ float g_K [BB * TK * HD];   // RoPE'd pooled K:       2 MB
__device__ float g_V [BB * TK * HD];   // pooled V:              2 MB
__device__ float g_of[BB * TT * HD];   // causal attn out:       8 MB
__device__ float g_or[BB * TT * HD];   // full attn out, PRE-FLIPPED in q: 8 MB

// ------------------- kernel 1: combined Q + fused-KV projection GEMM + RoPE -------------------
// One launch, grid = 320:
//   c in [0,256):   Q tile   (A = x rows;             W = Wq; RoPE period 4096, scale 1/sqrt(128))
//   c in [256,320): KV tile  (A = stride-4 mean of x; W = Wk & Wv staged together; K gets RoPE)
// Pooling is folded into KV A-staging. Global->shared staging is register-prefetched:
// LDGs for block kc+16 issue right after the data-ready barrier of block kc, so their
// latency overlaps the whole compute phase.
__global__ __launch_bounds__(256) void gemm_all(const float* __restrict__ x,
                                                const float* __restrict__ Wq,
                                                const float* __restrict__ Wk,
                                                const float* __restrict__ Wv) {
    __shared__ float As [16 * 68];    // A staged k-major: As[kk*68 + row], 64 rows + pad
    __shared__ float Ws [16 * 128];   // W (Wq or Wk) row-major
    __shared__ float Ws2[16 * 128];   // Wv row-major (KV tiles only)
    __shared__ float s_theta[64];     // correctly-rounded fp32 RoPE frequencies

    const int c   = blockIdx.x;
    const int tid = threadIdx.x;
    const bool isQ = (c < 256);

    const int row0   = isQ ? c * 64 : (c - 256) * 64;   // row in Q-space or pooled-space
    const int period = isQ ? TT : TK;
    const float scale = isQ ? 0.08838834764831845f : 1.0f;

    if (tid < 64) {
        // theta_i = 10000^(-i/64), computed in double then rounded once to fp32
        s_theta[tid] = (float)pow(10000.0, -(double)tid * (1.0 / 64.0));
    }

    const int tr = tid >> 4;          // 0..15: rows tr*4 .. tr*4+3
    const int tc = tid & 15;          // 0..15: cols tc*4..+3 and 64+tc*4..+3

    float acc[4][8];                  // Q or K accumulator
    float accv[4][8];                 // V accumulator (KV tiles)
#pragma unroll
    for (int i = 0; i < 4; ++i)
#pragma unroll
        for (int j = 0; j < 8; ++j) { acc[i][j] = 0.f; accv[i][j] = 0.f; }

    // A-load role (fixed): one (Q) or four (KV, averaged) float4 per thread per block
    const int lr  = tid >> 2;         // 0..63 row within tile
    const int lk4 = (tid & 3) * 4;    // k offset 0,4,8,12
    // W-load role (fixed): 2 float4 per thread per W matrix
    const int wk0 = tid >> 5,       wc0 = tid & 31;        // f = tid
    const int wk1 = (tid + 256) >> 5, wc1 = tid & 31;      // f = tid + 256

    // base x row for this thread's A-staging
    const int prow = row0 + lr;
    size_t xrow_base;
    if (isQ) {
        xrow_base = (size_t)prow * DM;                       // direct row
    } else {
        int bb = prow >> 10, tp = prow & 1023;               // pooled row -> 4 x rows
        xrow_base = (size_t)(bb * TT + tp * 4) * DM;
    }

    // ---- register prefetch buffers ----
    float4 apre[4];                   // Q uses [0]; KV uses [0..3]
    float4 wpre [2];                  // Wq or Wk
    float4 wpre2[2];                  // Wv (KV only)

    // prefetch block kc = 0
    {
        const int kc = 0;
        if (isQ) {
            apre[0] = *(const float4*)&x[xrow_base + kc + lk4];
            wpre[0] = *(const float4*)&Wq[(size_t)(kc + wk0) * HD + wc0 * 4];
            wpre[1] = *(const float4*)&Wq[(size_t)(kc + wk1) * HD + wc1 * 4];
        } else {
#pragma unroll
            for (int r = 0; r < 4; ++r)
                apre[r] = *(const float4*)&x[xrow_base + (size_t)r * DM + kc + lk4];
            wpre [0] = *(const float4*)&Wk[(size_t)(kc + wk0) * HD + wc0 * 4];
            wpre [1] = *(const float4*)&Wk[(size_t)(kc + wk1) * HD + wc1 * 4];
            wpre2[0] = *(const float4*)&Wv[(size_t)(kc + wk0) * HD + wc0 * 4];
            wpre2[1] = *(const float4*)&Wv[(size_t)(kc + wk1) * HD + wc1 * 4];
        }
    }

    for (int kc = 0; kc < DM; kc += 16) {
        // ---- STS from prefetch registers ----
        if (isQ) {
            As[(lk4 + 0) * 68 + lr] = apre[0].x;
            As[(lk4 + 1) * 68 + lr] = apre[0].y;
            As[(lk4 + 2) * 68 + lr] = apre[0].z;
            As[(lk4 + 3) * 68 + lr] = apre[0].w;
            *(float4*)&Ws[wk0 * 128 + wc0 * 4] = wpre[0];
            *(float4*)&Ws[wk1 * 128 + wc1 * 4] = wpre[1];
        } else {
            As[(lk4 + 0) * 68 + lr] = (apre[0].x + apre[1].x + apre[2].x + apre[3].x) * 0.25f;
            As[(lk4 + 1) * 68 + lr] = (apre[0].y + apre[1].y + apre[2].y + apre[3].y) * 0.25f;
            As[(lk4 + 2) * 68 + lr] = (apre[0].z + apre[1].z + apre[2].z + apre[3].z) * 0.25f;
            As[(lk4 + 3) * 68 + lr] = (apre[0].w + apre[1].w + apre[2].w + apre[3].w) * 0.25f;
            *(float4*)&Ws [wk0 * 128 + wc0 * 4] = wpre [0];
            *(float4*)&Ws [wk1 * 128 + wc1 * 4] = wpre [1];
            *(float4*)&Ws2[wk0 * 128 + wc0 * 4] = wpre2[0];
            *(float4*)&Ws2[wk1 * 128 + wc1 * 4] = wpre2[1];
        }
        __syncthreads();

        // ---- prefetch next block (overlaps the compute below) ----
        if (kc + 16 < DM) {
            const int kn = kc + 16;
            if (isQ) {
                apre[0] = *(const float4*)&x[xrow_base + kn + lk4];
                wpre[0] = *(const float4*)&Wq[(size_t)(kn + wk0) * HD + wc0 * 4];
                wpre[1] = *(const float4*)&Wq[(size_t)(kn + wk1) * HD + wc1 * 4];
            } else {
#pragma unroll
                for (int r = 0; r < 4; ++r)
                    apre[r] = *(const float4*)&x[xrow_base + (size_t)r * DM + kn + lk4];
                wpre [0] = *(const float4*)&Wk[(size_t)(kn + wk0) * HD + wc0 * 4];
                wpre [1] = *(const float4*)&Wk[(size_t)(kn + wk1) * HD + wc1 * 4];
                wpre2[0] = *(const float4*)&Wv[(size_t)(kn + wk0) * HD + wc0 * 4];
                wpre2[1] = *(const float4*)&Wv[(size_t)(kn + wk1) * HD + wc1 * 4];
            }
        }

        // ---- compute ----
        if (isQ) {
#pragma unroll
            for (int kk = 0; kk < 16; ++kk) {
                float4 a4 = *(float4*)&As[kk * 68 + tr * 4];    // warp-broadcast (2 distinct)
                float4 wa = *(float4*)&Ws[kk * 128 + tc * 4];
                float4 wb = *(float4*)&Ws[kk * 128 + 64 + tc * 4];
                float ar[4] = {a4.x, a4.y, a4.z, a4.w};
#pragma unroll
                for (int i = 0; i < 4; ++i) {
                    acc[i][0] += ar[i] * wa.x;
                    acc[i][1] += ar[i] * wa.y;
                    acc[i][2] += ar[i] * wa.z;
                    acc[i][3] += ar[i] * wa.w;
                    acc[i][4] += ar[i] * wb.x;
                    acc[i][5] += ar[i] * wb.y;
                    acc[i][6] += ar[i] * wb.z;
                    acc[i][7] += ar[i] * wb.w;
                }
            }
        } else {
#pragma unroll
            for (int kk = 0; kk < 16; ++kk) {
                float4 a4  = *(float4*)&As [kk * 68 + tr * 4];
                float4 wka = *(float4*)&Ws [kk * 128 + tc * 4];
                float4 wkb = *(float4*)&Ws [kk * 128 + 64 + tc * 4];
                float4 wva = *(float4*)&Ws2[kk * 128 + tc * 4];
                float4 wvb = *(float4*)&Ws2[kk * 128 + 64 + tc * 4];
                float ar[4] = {a4.x, a4.y, a4.z, a4.w};
#pragma unroll
                for (int i = 0; i < 4; ++i) {
                    acc[i][0]  += ar[i] * wka.x;
                    acc[i][1]  += ar[i] * wka.y;
                    acc[i][2]  += ar[i] * wka.z;
                    acc[i][3]  += ar[i] * wka.w;
                    acc[i][4]  += ar[i] * wkb.x;
                    acc[i][5]  += ar[i] * wkb.y;
                    acc[i][6]  += ar[i] * wkb.z;
                    acc[i][7]  += ar[i] * wkb.w;
                    accv[i][0] += ar[i] * wva.x;
                    accv[i][1] += ar[i] * wva.y;
                    accv[i][2] += ar[i] * wva.z;
                    accv[i][3] += ar[i] * wva.w;
                    accv[i][4] += ar[i] * wvb.x;
                    accv[i][5] += ar[i] * wvb.y;
                    accv[i][6] += ar[i] * wvb.z;
                    accv[i][7] += ar[i] * wvb.w;
                }
            }
        }
        __syncthreads();
    }

    // epilogue: RoPE pairs (i, i+64) are (acc[r][j], acc[r][j+4]) — all in-register
    float* __restrict__ C = isQ ? g_Q : g_K;
#pragma unroll
    for (int r = 0; r < 4; ++r) {
        int grow = row0 + tr * 4 + r;
        int t = grow % period;
        float ft = (float)t;
        float oa[8];
#pragma unroll
        for (int j = 0; j < 4; ++j) {
            float ang = ft * s_theta[tc * 4 + j];               // same fp32 op as reference
            float sn, cs;
            sincosf(ang, &sn, &cs);
            oa[j]     = (acc[r][j] * cs - acc[r][j + 4] * sn) * scale;
            oa[j + 4] = (acc[r][j + 4] * cs + acc[r][j] * sn) * scale;
        }
        float4 o1, o2;
        o1.x = oa[0]; o1.y = oa[1]; o1.z = oa[2]; o1.w = oa[3];
        o2.x = oa[4]; o2.y = oa[5]; o2.z = oa[6]; o2.w = oa[7];
        *(float4*)&C[(size_t)grow * HD + tc * 4]      = o1;
        *(float4*)&C[(size_t)grow * HD + 64 + tc * 4] = o2;
        if (!isQ) {
            float4 v1, v2;
            v1.x = accv[r][0]; v1.y = accv[r][1]; v1.z = accv[r][2]; v1.w = accv[r][3];
            v2.x = accv[r][4]; v2.y = accv[r][5]; v2.z = accv[r][6]; v2.w = accv[r][7];
            *(float4*)&g_V[(size_t)grow * HD + tc * 4]      = v1;
            *(float4*)&g_V[(size_t)grow * HD + 64 + tc * 4] = v2;
        }
    }
}

// ------------------- kernel 2: fused dual-softmax flash attention -------------------
// Per CTA: 64 queries of one batch. One S = Q*K^T pass feeds BOTH the causal (fwd)
// and the unmasked (rev) softmax. Exact identity: fwd state is a rescale of the rev
// running state at the boundary chunk, so fwd PV costs ONE chunk per query.
// K/V chunk staging is register-prefetched: chunk kc+1's LDGs issue right after the
// data-ready barrier of chunk kc, overlapping S/softmax/PV compute.
// The reverse-path output is written PRE-FLIPPED in q so the combine is fully linear.
__global__ __launch_bounds__(256, 1) void flash_kernel() {
    extern __shared__ float smf[];
    float* Qt = smf;                  // [128][68]  Q transposed (dim-major)
    float* Kt = Qt + 128 * 68;        // [128][68]
    float* Vs = Kt + 128 * 68;        // [64][128]
    float* Ss = Vs + 64 * 128;        // [64][65]  raw logits, q-major
    float* Pr = Ss + 64 * 65;         // [64][68]  rev probs, j-major (transposed)
    float* Pf = Pr + 64 * 68;         // [64][68]  fwd probs (boundary chunk only)
    float* cS = Pf + 64 * 68;         // [64] per-query rev correction this chunk
    float* fS = cS + 64;              // [64] per-query fwd rescale (boundary)
    float* iLf = fS + 64;             // [64]
    float* iLr = iLf + 64;            // [64]

    const int b  = blockIdx.y;
    const int bx = blockIdx.x;
    const int q0 = bx * 64;
    const int tid = threadIdx.x;

    // load Q tile transposed (scaled + RoPE'd already)
    for (int f = tid; f < 2048; f += 256) {
        int d4 = f >> 6, q = f & 63;
        float4 v = *(const float4*)&g_Q[((size_t)b * TT + q0 + q) * HD + d4 * 4];
        int base = (d4 * 4) * 68 + q;
        Qt[base]       = v.x;
        Qt[base + 68]  = v.y;
        Qt[base + 136] = v.z;
        Qt[base + 204] = v.w;
    }

    // roles
    const int qs = tid >> 2;                   // softmax: owned query row
    const int g  = tid & 3;                    // softmax: column quarter (16 keys)
    const int lim_s = 16 * bx + (qs >> 2);     // causal key limit for query qs
    const int kcp_s = lim_s >> 6;              // boundary chunk for query qs
    const unsigned qmask = 0xFu << (tid & 28); // quad-scoped shuffle mask

    const int tq4 = (tid >> 4) << 2;           // S-compute 4x4 micro-tile
    const int tj4 = (tid & 15) << 2;

    const int qg = tid >> 4;                   // PV: 4 queries qg*4..+3
    const int dg = tid & 15;                   // PV: dims dg*4..+3 and 64+dg*4..+3
    const int kcp_v = (16 * bx + qg) >> 6;     // boundary chunk (uniform per thread)

    // K/V staging roles (fixed, f = tid + 256*i)
    const size_t kvbase = (size_t)b * TK * HD;

    float m_r = NEGF, l_r = 0.f, l_f = 1.f;
    float accr[32], accf[32];
#pragma unroll
    for (int i = 0; i < 32; ++i) { accr[i] = 0.f; accf[i] = 0.f; }

    // ---- prefetch chunk 0 into registers ----
    float4 kpre[8], vpre[8];
#pragma unroll
    for (int i = 0; i < 8; ++i) {
        int f = tid + 256 * i;
        int d4 = f >> 6, j = f & 63;
        kpre[i] = *(const float4*)&g_K[kvbase + (size_t)j * HD + d4 * 4];
        int jv = f >> 5, dv = f & 31;
        vpre[i] = *(const float4*)&g_V[kvbase + (size_t)jv * HD + dv * 4];
    }

    for (int kc = 0; kc < 16; ++kc) {
        const int j0 = kc * 64;
        __syncthreads();                       // prior chunk's smem readers done (Qt ready at kc=0)

        // ---- STS K/V from prefetch registers ----
#pragma unroll
        for (int i = 0; i < 8; ++i) {
            int f = tid + 256 * i;
            int d4 = f >> 6, j = f & 63;
            int base = (d4 * 4) * 68 + j;
            Kt[base]       = kpre[i].x;
            Kt[base + 68]  = kpre[i].y;
            Kt[base + 136] = kpre[i].z;
            Kt[base + 204] = kpre[i].w;
            int jv = f >> 5, dv = f & 31;
            *(float4*)&Vs[jv * 128 + dv * 4] = vpre[i];
        }
        __syncthreads();

        // ---- prefetch chunk kc+1 (overlaps all compute below) ----
        if (kc < 15) {
            const int j1 = j0 + 64;
#pragma unroll
            for (int i = 0; i < 8; ++i) {
                int f = tid + 256 * i;
                int d4 = f >> 6, j = f & 63;
                kpre[i] = *(const float4*)&g_K[kvbase + (size_t)(j1 + j) * HD + d4 * 4];
                int jv = f >> 5, dv = f & 31;
                vpre[i] = *(const float4*)&g_V[kvbase + (size_t)(j1 + jv) * HD + dv * 4];
            }
        }

        // ---- S = Q K^T (4x4 per thread, dim-major float4 loads) ----
        {
            float sc[4][4];
#pragma unroll
            for (int i = 0; i < 4; ++i)
#pragma unroll
                for (int l = 0; l < 4; ++l) sc[i][l] = 0.f;
#pragma unroll 4
            for (int d = 0; d < 128; ++d) {
                float4 qv = *(float4*)&Qt[d * 68 + tq4];
                float4 kv = *(float4*)&Kt[d * 68 + tj4];
                sc[0][0] += qv.x * kv.x; sc[0][1] += qv.x * kv.y; sc[0][2] += qv.x * kv.z; sc[0][3] += qv.x * kv.w;
                sc[1][0] += qv.y * kv.x; sc[1][1] += qv.y * kv.y; sc[1][2] += qv.y * kv.z; sc[1][3] += qv.y * kv.w;
                sc[2][0] += qv.z * kv.x; sc[2][1] += qv.z * kv.y; sc[2][2] += qv.z * kv.z; sc[2][3] += qv.z * kv.w;
                sc[3][0] += qv.w * kv.x; sc[3][1] += qv.w * kv.y; sc[3][2] += qv.w * kv.z; sc[3][3] += qv.w * kv.w;
            }
#pragma unroll
            for (int i = 0; i < 4; ++i)
#pragma unroll
                for (int l = 0; l < 4; ++l)
                    Ss[(tq4 + i) * 65 + tj4 + l] = sc[i][l];
        }
        __syncthreads();

        // ---- softmax (quad of 4 threads per query row) ----
        {
            float sv[16];
#pragma unroll
            for (int mI = 0; mI < 16; ++mI) sv[mI] = Ss[qs * 65 + g * 16 + mI];

            float m_pre = m_r, l_pre = l_r;

            // rev (unmasked) online update
            float mloc = NEGF;
#pragma unroll
            for (int mI = 0; mI < 16; ++mI) mloc = fmaxf(mloc, sv[mI]);
            mloc = fmaxf(mloc, __shfl_xor_sync(qmask, mloc, 1));
            mloc = fmaxf(mloc, __shfl_xor_sync(qmask, mloc, 2));
            float mnew = fmaxf(m_r, mloc);
            float corr = __expf(m_r - mnew);
            float sum = 0.f;
#pragma unroll
            for (int mI = 0; mI < 16; ++mI) {
                float p = __expf(sv[mI] - mnew);
                sum += p;
                Pr[(g * 16 + mI) * 68 + qs] = p;
            }
            sum += __shfl_xor_sync(qmask, sum, 1);
            sum += __shfl_xor_sync(qmask, sum, 2);
            l_r = l_r * corr + sum;
            m_r = mnew;
            if (g == 0) cS[qs] = corr;

            // fwd: only at the boundary chunk, rescaled from the rev pre-state
            if (kc == kcp_s) {
                float mlf = NEGF;
#pragma unroll
                for (int mI = 0; mI < 16; ++mI) {
                    int j = j0 + g * 16 + mI;
                    if (j <= lim_s) mlf = fmaxf(mlf, sv[mI]);
                }
                mlf = fmaxf(mlf, __shfl_xor_sync(qmask, mlf, 1));
                mlf = fmaxf(mlf, __shfl_xor_sync(qmask, mlf, 2));
                float mnf = fmaxf(m_pre, mlf);
                float cf = __expf(m_pre - mnf);   // rescale of all prior (fully-allowed) chunks
                float sf = 0.f;
#pragma unroll
                for (int mI = 0; mI < 16; ++mI) {
                    int j = j0 + g * 16 + mI;
                    float p = (j <= lim_s) ? __expf(sv[mI] - mnf) : 0.f;
                    sf += p;
                    Pf[(g * 16 + mI) * 68 + qs] = p;
                }
                sf += __shfl_xor_sync(qmask, sf, 1);
                sf += __shfl_xor_sync(qmask, sf, 2);
                l_f = l_pre * cf + sf;
                if (g == 0) fS[qs] = cf;
            }
        }
        __syncthreads();

        // ---- PV: P^T (64x64, j-major) x V (64x128), thread = 4q x 8d ----
        {
            float4 c4v = *(float4*)&cS[qg * 4];
            float cc[4] = {c4v.x, c4v.y, c4v.z, c4v.w};
            if (kc == kcp_v) {
                float4 f4v = *(float4*)&fS[qg * 4];
                float ff[4] = {f4v.x, f4v.y, f4v.z, f4v.w};
#pragma unroll
                for (int qi = 0; qi < 4; ++qi)
#pragma unroll
                    for (int d = 0; d < 8; ++d)
                        accf[qi * 8 + d] = accr[qi * 8 + d] * ff[qi];   // rev pre-state rescaled
            }
#pragma unroll
            for (int qi = 0; qi < 4; ++qi)
#pragma unroll
                for (int d = 0; d < 8; ++d)
                    accr[qi * 8 + d] *= cc[qi];

            if (kc == kcp_v) {
#pragma unroll 2
                for (int j = 0; j < 64; ++j) {
                    float4 pr4 = *(float4*)&Pr[j * 68 + qg * 4];
                    float4 pf4 = *(float4*)&Pf[j * 68 + qg * 4];
                    float4 va = *(float4*)&Vs[j * 128 + dg * 4];
                    float4 vb = *(float4*)&Vs[j * 128 + 64 + dg * 4];
                    float prv[4] = {pr4.x, pr4.y, pr4.z, pr4.w};
                    float pfv[4] = {pf4.x, pf4.y, pf4.z, pf4.w};
#pragma unroll
                    for (int qi = 0; qi < 4; ++qi) {
                        accr[qi * 8 + 0] += prv[qi] * va.x;
                        accr[qi * 8 + 1] += prv[qi] * va.y;
                        accr[qi * 8 + 2] += prv[qi] * va.z;
                        accr[qi * 8 + 3] += prv[qi] * va.w;
                        accr[qi * 8 + 4] += prv[qi] * vb.x;
                        accr[qi * 8 + 5] += prv[qi] * vb.y;
                        accr[qi * 8 + 6] += prv[qi] * vb.z;
                        accr[qi * 8 + 7] += prv[qi] * vb.w;
                        accf[qi * 8 + 0] += pfv[qi] * va.x;
                        accf[qi * 8 + 1] += pfv[qi] * va.y;
                        accf[qi * 8 + 2] += pfv[qi] * va.z;
                        accf[qi * 8 + 3] += pfv[qi] * va.w;
                        accf[qi * 8 + 4] += pfv[qi] * vb.x;
                        accf[qi * 8 + 5] += pfv[qi] * vb.y;
                        accf[qi * 8 + 6] += pfv[qi] * vb.z;
                        accf[qi * 8 + 7] += pfv[qi] * vb.w;
                    }
                }
            } else {
#pragma unroll 2
                for (int j = 0; j < 64; ++j) {
                    float4 pr4 = *(float4*)&Pr[j * 68 + qg * 4];
                    float4 va = *(float4*)&Vs[j * 128 + dg * 4];
                    float4 vb = *(float4*)&Vs[j * 128 + 64 + dg * 4];
                    float prv[4] = {pr4.x, pr4.y, pr4.z, pr4.w};
#pragma unroll
                    for (int qi = 0; qi < 4; ++qi) {
                        accr[qi * 8 + 0] += prv[qi] * va.x;
                        accr[qi * 8 + 1] += prv[qi] * va.y;
                        accr[qi * 8 + 2] += prv[qi] * va.z;
                        accr[qi * 8 + 3] += prv[qi] * va.w;
                        accr[qi * 8 + 4] += prv[qi] * vb.x;
                        accr[qi * 8 + 5] += prv[qi] * vb.y;
                        accr[qi * 8 + 6] += prv[qi] * vb.z;
                        accr[qi * 8 + 7] += prv[qi] * vb.w;
                    }
                }
            }
        }
    }

    // ---- epilogue ----
    if (g == 0) {
        iLr[qs] = 1.f / l_r;
        iLf[qs] = 1.f / l_f;
    }
    __syncthreads();
    {
        float4 ir4 = *(float4*)&iLr[qg * 4];
        float4 if4 = *(float4*)&iLf[qg * 4];
        float irr[4] = {ir4.x, ir4.y, ir4.z, ir4.w};
        float iff[4] = {if4.x, if4.y, if4.z, if4.w};
#pragma unroll
        for (int qi = 0; qi < 4; ++qi) {
            int qrow = q0 + qg * 4 + qi;
            size_t base  = ((size_t)b * TT + qrow) * HD;                 // fwd: natural order
            size_t baser = ((size_t)b * TT + (TT - 1 - qrow)) * HD;      // rev: pre-flipped in q
            float4 v;
            v.x = accf[qi * 8 + 0] * iff[qi]; v.y = accf[qi * 8 + 1] * iff[qi];
            v.z = accf[qi * 8 + 2] * iff[qi]; v.w = accf[qi * 8 + 3] * iff[qi];
            *(float4*)&g_of[base + dg * 4] = v;
            v.x = accf[qi * 8 + 4] * iff[qi]; v.y = accf[qi * 8 + 5] * iff[qi];
            v.z = accf[qi * 8 + 6] * iff[qi]; v.w = accf[qi * 8 + 7] * iff[qi];
            *(float4*)&g_of[base + 64 + dg * 4] = v;
            v.x = accr[qi * 8 + 0] * irr[qi]; v.y = accr[qi * 8 + 1] * irr[qi];
            v.z = accr[qi * 8 + 2] * irr[qi]; v.w = accr[qi * 8 + 3] * irr[qi];
            *(float4*)&g_or[baser + dg * 4] = v;
            v.x = accr[qi * 8 + 4] * irr[qi]; v.y = accr[qi * 8 + 5] * irr[qi];
            v.z = accr[qi * 8 + 6] * irr[qi]; v.w = accr[qi * 8 + 7] * irr[qi];
            *(float4*)&g_or[baser + 64 + dg * 4] = v;
        }
    }
}

// ------------------- kernel 3: blend (both buffers already q-aligned) -------------------
__global__ __launch_bounds__(256) void combine_kernel(const float* __restrict__ flux,
                                                      float* __restrict__ out) {
    int idx = blockIdx.x * 256 + threadIdx.x;      // float4 index
    const int n4 = BB * TT * HD / 4;               // 524,288
    if (idx >= n4) return;
    float a = 1.f / (1.f + expf(-flux[0]));
    float oma = 1.f - a;
    float4 f = ((const float4*)g_of)[idx];
    float4 r = ((const float4*)g_or)[idx];         // pre-flipped by flash epilogue
    float4 o;
    o.x = a * f.x + oma * r.x;
    o.y = a * f.y + oma * r.y;
    o.z = a * f.z + oma * r.z;
    o.w = a * f.w + oma * r.w;
    ((float4*)out)[idx] = o;
}

// ------------------- launch -------------------
extern "C" void kernel_launch(void* const* d_in, const int* in_sizes, int n_in,
                              void* d_out, int out_size) {
    const float* x    = (const float*)d_in[0];
    const float* Wq   = (const float*)d_in[1];
    const float* Wk   = (const float*)d_in[2];
    const float* Wv   = (const float*)d_in[3];
    // d_in[4..8] (band_weights, W1, b1, W2, b2) are provably no-ops: the spectral
    // gate is a per-(b,q) scalar added before a shift-invariant softmax.
    const float* flux = (const float*)d_in[9];
    float* out = (float*)d_out;

    // Q + fused-KV projections + RoPE in ONE launch (256 Q tiles, 64 KV tiles);
    // the stride-4 pooling is folded into the KV tiles' A-staging.
    gemm_all<<<320, 256>>>(x, Wq, Wk, Wv);

    // fused causal + full attention
    // Qt+Kt: 2*128*68, Vs: 64*128, Ss: 64*65, Pr+Pf: 2*64*68, scalars: 4*64
    const int FLASH_SMEM = (2 * 128 * 68 + 64 * 128 + 64 * 65 + 2 * 64 * 68 + 256) * 4; // 154,880 B
    cudaFuncSetAttribute(flash_kernel, cudaFuncAttributeMaxDynamicSharedMemorySize, FLASH_SMEM);
    flash_kernel<<<dim3(64, BB), 256, FLASH_SMEM>>>();

    // out = sigmoid(alpha)*O_fwd + (1-sigmoid(alpha))*O_rev_flipped  (linear blend)
    combine_kernel<<<2048, 256>>>(flux, out);
}